// round 2
// baseline (speedup 1.0000x reference)
#include <cuda_runtime.h>
#include <cstdint>
#include <cstddef>

#define T_STEPS 512
#define B_BATCH 128
#define D_IN    512
#define H_DIM   512
#define NB      128   // persistent grid size (<= SM count, all co-resident)

// Scratch (allocation-free rule: __device__ globals)
__device__ float    g_xproj[(size_t)T_STEPS * B_BATCH * 3 * H_DIM]; // [T,B,3H] fp32
__device__ unsigned g_bar[T_STEPS];

// ---------- packed f32x2 helpers (sm_103a FFMA2) ----------
static __device__ __forceinline__ unsigned long long pack2(float lo, float hi) {
    unsigned long long r;
    asm("mov.b64 %0, {%1, %2};" : "=l"(r) : "f"(lo), "f"(hi));
    return r;
}
static __device__ __forceinline__ void fma2(unsigned long long& d,
                                            unsigned long long a,
                                            unsigned long long b) {
    asm("fma.rn.f32x2 %0, %1, %2, %0;" : "+l"(d) : "l"(a), "l"(b));
}
static __device__ __forceinline__ float2 unpack2(unsigned long long v) {
    float2 f;
    asm("mov.b64 {%0, %1}, %2;" : "=f"(f.x), "=f"(f.y) : "l"(v));
    return f;
}

// ---------- barrier-counter reset (per graph replay) ----------
__global__ void init_bar_kernel() {
    if (threadIdx.x < T_STEPS) g_bar[threadIdx.x] = 0u;
}

// ---------- x_proj GEMM: C[65536,1536] = A[65536,512] * Wi[512,1536] + bi ----------
__global__ __launch_bounds__(256) void xproj_kernel(const float* __restrict__ A,
                                                    const float* __restrict__ Wi,
                                                    const float* __restrict__ bi) {
    __shared__ __align__(16) float As[16][68];   // transposed: As[k][m]
    __shared__ __align__(16) float Bs[16][64];   // Bs[k][n]
    const int tid = threadIdx.x;
    const int tx = tid & 15;        // n sub-tile
    const int ty = tid >> 4;        // m sub-tile
    const int m0 = blockIdx.y * 64;
    const int n0 = blockIdx.x * 64;

    const int ar = tid >> 2;            // 0..63 : row of A tile
    const int ac = (tid & 3) * 4;       // 0,4,8,12 : col group
    const int br = tid >> 4;            // 0..15 : row of B tile
    const int bc = (tid & 15) * 4;      // col group

    unsigned long long acc[4][2];
#pragma unroll
    for (int i = 0; i < 4; ++i) { acc[i][0] = 0ull; acc[i][1] = 0ull; }

    for (int k0 = 0; k0 < D_IN; k0 += 16) {
        float4 va = *(const float4*)&A[(size_t)(m0 + ar) * D_IN + k0 + ac];
        float4 vb = *(const float4*)&Wi[(size_t)(k0 + br) * 1536 + n0 + bc];
        As[ac + 0][ar] = va.x;
        As[ac + 1][ar] = va.y;
        As[ac + 2][ar] = va.z;
        As[ac + 3][ar] = va.w;
        *(float4*)&Bs[br][bc] = vb;
        __syncthreads();
#pragma unroll
        for (int k = 0; k < 16; ++k) {
            unsigned long long b01 = *(const unsigned long long*)&Bs[k][tx * 4];
            unsigned long long b23 = *(const unsigned long long*)&Bs[k][tx * 4 + 2];
#pragma unroll
            for (int i = 0; i < 4; ++i) {
                float a = As[k][ty * 4 + i];
                unsigned long long a2 = pack2(a, a);
                fma2(acc[i][0], a2, b01);
                fma2(acc[i][1], a2, b23);
            }
        }
        __syncthreads();
    }

    float4 bv = *(const float4*)&bi[n0 + tx * 4];
#pragma unroll
    for (int i = 0; i < 4; ++i) {
        float2 p0 = unpack2(acc[i][0]);
        float2 p1 = unpack2(acc[i][1]);
        float4 o;
        o.x = p0.x + bv.x;
        o.y = p0.y + bv.y;
        o.z = p1.x + bv.z;
        o.w = p1.y + bv.w;
        *(float4*)&g_xproj[(size_t)(m0 + ty * 4 + i) * 1536 + n0 + tx * 4] = o;
    }
}

// ---------- persistent GRU scan ----------
// CTA = (mi in 0..3: 32 batch rows) x (hs in 0..31: 16 hidden cols).
// Recurrent weight slice (48 cols x K=512) resident in SMEM for all 512 steps.
__global__ __launch_bounds__(256) void gru_kernel(const int* __restrict__ resets,
                                                  const float* __restrict__ h0,
                                                  const float* __restrict__ Whrz,
                                                  const float* __restrict__ Whn,
                                                  const float* __restrict__ bhn,
                                                  float* __restrict__ out) {
    extern __shared__ float smem[];
    float* Wt = smem;                    // [48][514] transposed weights (K contiguous)
    float* Hs = smem + 48 * 514;         // [32][512] masked h tile

    const int tid = threadIdx.x;
    const int mi = blockIdx.x >> 5;      // 0..3
    const int hs = blockIdx.x & 31;      // 0..31

    float* hT = out;                             // [B,H]
    float* ys = out + (size_t)B_BATCH * H_DIM;   // [T,B,H]

    // Load weight slice once, transposed: Wt[c][k]; c = gate*16 + local col.
    for (int idx = tid; idx < 48 * 512; idx += 256) {
        int c = idx >> 9;
        int k = idx & 511;
        int g = c >> 4;
        int cc = c & 15;
        int col = hs * 16 + cc;
        float v;
        if (g == 0)      v = Whrz[(size_t)k * 1024 + col];
        else if (g == 1) v = Whrz[(size_t)k * 1024 + 512 + col];
        else             v = Whn[(size_t)k * 512 + col];
        Wt[c * 514 + k] = v;
    }

    const int tx = tid & 15;             // local hidden col
    const int ty = tid >> 4;             // row pair
    const int j = hs * 16 + tx;          // global hidden col
    const float bn_bias = bhn[j];
    const int r0 = ty * 2, r1 = r0 + 1;  // local rows
    const int b0g = mi * 32 + r0;        // global batch rows
    const int b1g = b0g + 1;

    const float* wr = Wt + (size_t)tx * 514;
    const float* wz = Wt + (size_t)(16 + tx) * 514;
    const float* wn = Wt + (size_t)(32 + tx) * 514;
    const float* hp0 = Hs + r0 * 512;
    const float* hp1 = Hs + r1 * 512;

    __syncthreads();

    for (int t = 0; t < T_STEPS; ++t) {
        // ---- load masked h tile (from h0 at t=0, else ys[t-1]) via L2 ----
        const float* hsrc = (t == 0)
            ? (h0 + (size_t)(mi * 32) * H_DIM)
            : (ys + ((size_t)(t - 1) * B_BATCH + mi * 32) * H_DIM);
        for (int idx = tid; idx < 32 * 256; idx += 256) {
            int row = idx >> 8;
            int k2 = idx & 255;
            float2 v = __ldcg((const float2*)(hsrc + (size_t)row * H_DIM) + k2);
            if (resets[t * B_BATCH + mi * 32 + row] != 0) { v.x = 0.f; v.y = 0.f; }
            *((float2*)(Hs + row * 512) + k2) = v;
        }
        __syncthreads();

        // ---- recurrent GEMM for 2 rows x 3 gates (FFMA2, packed along K) ----
        unsigned long long a_hr0 = 0ull, a_hz0 = 0ull, a_hn0 = 0ull;
        unsigned long long a_hr1 = 0ull, a_hz1 = 0ull, a_hn1 = 0ull;
#pragma unroll 8
        for (int k2 = 0; k2 < 256; ++k2) {
            unsigned long long a0 = *(const unsigned long long*)(hp0 + 2 * k2);
            unsigned long long a1 = *(const unsigned long long*)(hp1 + 2 * k2);
            unsigned long long br_ = *(const unsigned long long*)(wr + 2 * k2);
            unsigned long long bz_ = *(const unsigned long long*)(wz + 2 * k2);
            unsigned long long bn_ = *(const unsigned long long*)(wn + 2 * k2);
            fma2(a_hr0, a0, br_); fma2(a_hz0, a0, bz_); fma2(a_hn0, a0, bn_);
            fma2(a_hr1, a1, br_); fma2(a_hz1, a1, bz_); fma2(a_hn1, a1, bn_);
        }
        float2 p;
        p = unpack2(a_hr0); float hr0 = p.x + p.y;
        p = unpack2(a_hz0); float hz0 = p.x + p.y;
        p = unpack2(a_hn0); float hn0 = p.x + p.y;
        p = unpack2(a_hr1); float hr1 = p.x + p.y;
        p = unpack2(a_hz1); float hz1 = p.x + p.y;
        p = unpack2(a_hn1); float hn1 = p.x + p.y;

        // ---- gates + state update (thread owns (b, j) fully) ----
#pragma unroll
        for (int rr = 0; rr < 2; ++rr) {
            const int   bg = rr ? b1g : b0g;
            const int   rl = rr ? r1 : r0;
            const float hrv = rr ? hr1 : hr0;
            const float hzv = rr ? hz1 : hz0;
            const float hnv = rr ? hn1 : hn0;
            const float* xb = g_xproj + ((size_t)t * B_BATCH + bg) * 1536 + j;
            float xr = xb[0], xz = xb[512], xn = xb[1024];
            float hprev = Hs[rl * 512 + j];   // already reset-masked
            float rg = 1.f / (1.f + __expf(-(xr + hrv)));
            float zg = 1.f / (1.f + __expf(-(xz + hzv)));
            float ng = tanhf(xn + rg * (hnv + bn_bias));
            float hnew = (1.f - zg) * ng + zg * hprev;
            ys[((size_t)t * B_BATCH + bg) * H_DIM + j] = hnew;
            if (t == T_STEPS - 1) hT[(size_t)bg * H_DIM + j] = hnew;
        }

        // ---- grid barrier (all 128 CTAs co-resident; replay-safe counters) ----
        __threadfence();
        __syncthreads();
        if (tid == 0) {
            unsigned prev = atomicAdd(&g_bar[t], 1u);
            if (prev + 1u < NB) {
                volatile unsigned* vb = &g_bar[t];
                while (*vb < NB) __nanosleep(64);
            }
        }
        __syncthreads();
    }
}

extern "C" void kernel_launch(void* const* d_in, const int* in_sizes, int n_in,
                              void* d_out, int out_size) {
    const float* ins    = (const float*)d_in[0];   // [T,B,D]
    const int*   resets = (const int*)  d_in[1];   // [T,B] (bool -> int32)
    const float* h0     = (const float*)d_in[2];   // [B,H]
    const float* Wi     = (const float*)d_in[3];   // [D,3H]
    const float* bi     = (const float*)d_in[4];   // [3H]
    const float* Whrz   = (const float*)d_in[5];   // [H,2H]
    const float* Whn    = (const float*)d_in[6];   // [H,H]
    const float* bhn    = (const float*)d_in[7];   // [H]
    float* out = (float*)d_out;                    // [B*H] hT, then [T,B,H] ys

    (void)in_sizes; (void)n_in; (void)out_size;

    static bool attr_set = false;
    if (!attr_set) {
        cudaFuncSetAttribute(gru_kernel,
                             cudaFuncAttributeMaxDynamicSharedMemorySize,
                             (48 * 514 + 32 * 512) * (int)sizeof(float));
        attr_set = true;
    }

    init_bar_kernel<<<1, T_STEPS>>>();
    {
        dim3 grid(1536 / 64, (T_STEPS * B_BATCH) / 64);
        xproj_kernel<<<grid, 256>>>(ins, Wi, bi);
    }
    gru_kernel<<<NB, 256, (48 * 514 + 32 * 512) * sizeof(float)>>>(
        resets, h0, Whrz, Whn, bhn, out);
}

// round 3
// speedup vs baseline: 1.1858x; 1.1858x over previous
#include <cuda_runtime.h>
#include <cstdint>
#include <cstddef>

#define T_STEPS 512
#define B_BATCH 128
#define D_IN    512
#define H_DIM   512

// Scratch (allocation-free rule: __device__ globals)
__device__ float    g_xproj[(size_t)T_STEPS * B_BATCH * 3 * H_DIM]; // [T,B,3H]
__device__ unsigned g_bar[T_STEPS][4][2];                           // [t][mi][khalf]

// ---------- packed f32x2 helpers (sm_103a FFMA2) ----------
static __device__ __forceinline__ unsigned long long pack2(float lo, float hi) {
    unsigned long long r;
    asm("mov.b64 %0, {%1, %2};" : "=l"(r) : "f"(lo), "f"(hi));
    return r;
}
static __device__ __forceinline__ void fma2(unsigned long long& d,
                                            unsigned long long a,
                                            unsigned long long b) {
    asm("fma.rn.f32x2 %0, %1, %2, %0;" : "+l"(d) : "l"(a), "l"(b));
}
static __device__ __forceinline__ float2 unpack2(unsigned long long v) {
    float2 f;
    asm("mov.b64 {%0, %1}, %2;" : "=f"(f.x), "=f"(f.y) : "l"(v));
    return f;
}

// ---------- barrier-counter reset (per graph replay) ----------
__global__ void init_bar_kernel() {
    int i = blockIdx.x * blockDim.x + threadIdx.x;
    if (i < T_STEPS * 8) ((unsigned*)g_bar)[i] = 0u;
}

// ---------- x_proj GEMM: C[65536,1536] = A[65536,512] @ Wi[512,1536] + bi ----------
// 128x128x16 tiles, 8x8 per thread, double-buffered smem, FFMA2.
__global__ __launch_bounds__(256) void xproj_kernel(const float* __restrict__ A,
                                                    const float* __restrict__ W,
                                                    const float* __restrict__ bi) {
    __shared__ __align__(16) float As[2][16][132];  // transposed: As[k][m], padded
    __shared__ __align__(16) float Bs[2][16][128];  // Bs[k][n]

    const int tid = threadIdx.x;
    const int m0 = blockIdx.y * 128;
    const int n0 = blockIdx.x * 128;
    const int tx = tid & 15;        // col block (8 cols)
    const int ty = tid >> 4;        // row block (8 rows)

    // global load mapping
    const int arow = tid >> 1;            // 0..127
    const int acol = (tid & 1) << 3;      // 0 or 8
    const int brow = tid >> 5;            // 0..7 (and +8)
    const int bcol = (tid & 31) << 2;     // 0..124 step 4

    const float* Ag = A + (size_t)(m0 + arow) * D_IN + acol;
    const float* Bg = W + (size_t)brow * 1536 + n0 + bcol;

    unsigned long long acc[8][4];
#pragma unroll
    for (int i = 0; i < 8; ++i)
#pragma unroll
        for (int jj = 0; jj < 4; ++jj) acc[i][jj] = 0ull;

    // prologue: load k-tile 0 into buffer 0
    float4 ra0 = *(const float4*)(Ag);
    float4 ra1 = *(const float4*)(Ag + 4);
    float4 rb0 = *(const float4*)(Bg);
    float4 rb1 = *(const float4*)(Bg + 8 * 1536);
    As[0][acol + 0][arow] = ra0.x;
    As[0][acol + 1][arow] = ra0.y;
    As[0][acol + 2][arow] = ra0.z;
    As[0][acol + 3][arow] = ra0.w;
    As[0][acol + 4][arow] = ra1.x;
    As[0][acol + 5][arow] = ra1.y;
    As[0][acol + 6][arow] = ra1.z;
    As[0][acol + 7][arow] = ra1.w;
    *(float4*)&Bs[0][brow][bcol] = rb0;
    *(float4*)&Bs[0][brow + 8][bcol] = rb1;
    __syncthreads();

    int buf = 0;
    for (int kt = 0; kt < 32; ++kt) {
        if (kt < 31) {
            const float* Ag2 = Ag + (kt + 1) * 16;
            const float* Bg2 = Bg + (size_t)(kt + 1) * 16 * 1536;
            ra0 = *(const float4*)(Ag2);
            ra1 = *(const float4*)(Ag2 + 4);
            rb0 = *(const float4*)(Bg2);
            rb1 = *(const float4*)(Bg2 + 8 * 1536);
        }
#pragma unroll
        for (int k = 0; k < 16; ++k) {
            ulonglong2 bA = *(const ulonglong2*)&Bs[buf][k][tx * 8];
            ulonglong2 bB = *(const ulonglong2*)&Bs[buf][k][tx * 8 + 4];
            float4 a03 = *(const float4*)&As[buf][k][ty * 8];
            float4 a47 = *(const float4*)&As[buf][k][ty * 8 + 4];
            float av[8] = {a03.x, a03.y, a03.z, a03.w, a47.x, a47.y, a47.z, a47.w};
#pragma unroll
            for (int i = 0; i < 8; ++i) {
                unsigned long long a2 = pack2(av[i], av[i]);
                fma2(acc[i][0], a2, bA.x);
                fma2(acc[i][1], a2, bA.y);
                fma2(acc[i][2], a2, bB.x);
                fma2(acc[i][3], a2, bB.y);
            }
        }
        if (kt < 31) {
            int nb = buf ^ 1;
            As[nb][acol + 0][arow] = ra0.x;
            As[nb][acol + 1][arow] = ra0.y;
            As[nb][acol + 2][arow] = ra0.z;
            As[nb][acol + 3][arow] = ra0.w;
            As[nb][acol + 4][arow] = ra1.x;
            As[nb][acol + 5][arow] = ra1.y;
            As[nb][acol + 6][arow] = ra1.z;
            As[nb][acol + 7][arow] = ra1.w;
            *(float4*)&Bs[nb][brow][bcol] = rb0;
            *(float4*)&Bs[nb][brow + 8][bcol] = rb1;
            __syncthreads();
            buf = nb;
        }
    }

    float4 bv0 = *(const float4*)&bi[n0 + tx * 8];
    float4 bv1 = *(const float4*)&bi[n0 + tx * 8 + 4];
#pragma unroll
    for (int i = 0; i < 8; ++i) {
        float2 p0 = unpack2(acc[i][0]);
        float2 p1 = unpack2(acc[i][1]);
        float2 p2 = unpack2(acc[i][2]);
        float2 p3 = unpack2(acc[i][3]);
        float4 o0, o1;
        o0.x = p0.x + bv0.x; o0.y = p0.y + bv0.y;
        o0.z = p1.x + bv0.z; o0.w = p1.y + bv0.w;
        o1.x = p2.x + bv1.x; o1.y = p2.y + bv1.y;
        o1.z = p3.x + bv1.z; o1.w = p3.y + bv1.w;
        float* dst = g_xproj + (size_t)(m0 + ty * 8 + i) * 1536 + n0 + tx * 8;
        *(float4*)dst = o0;
        *(float4*)(dst + 4) = o1;
    }
}

// ---------- persistent GRU scan ----------
// 128 CTAs, CTA = (mi: 32 batch rows) x (hs: 16 hidden cols).
// Weights [48 cols x 512 K] SMEM-resident for the whole kernel.
// Dependency: CTA (mi,hs) at step t needs only group-mi producers of step t-1,
// split by K-half -> per-(mi,half) counters of 16 arrivals each.
#define WSTR 516
__global__ __launch_bounds__(256) void gru_kernel(const int* __restrict__ resets,
                                                  const float* __restrict__ h0,
                                                  const float* __restrict__ Whrz,
                                                  const float* __restrict__ Whn,
                                                  const float* __restrict__ bhn,
                                                  float* out) {
    extern __shared__ float smem[];
    float* Wt = smem;                         // [48][WSTR]
    float* Hs = smem + 48 * WSTR;             // [32][512]
    __shared__ int rst_s[32];

    const int tid = threadIdx.x;
    const int mi = blockIdx.x >> 5;           // 0..3
    const int hs = blockIdx.x & 31;           // 0..31
    const int half_id = hs >> 4;              // which K-half this CTA produces

    float* hT = out;                             // [B,H]
    float* ys = out + (size_t)B_BATCH * H_DIM;   // [T,B,H]

    // one-time: weight slice into smem, transposed (K contiguous)
    for (int idx = tid; idx < 48 * 512; idx += 256) {
        int c = idx >> 9;
        int k = idx & 511;
        int g = c >> 4;
        int cc = c & 15;
        int col = hs * 16 + cc;
        float v;
        if (g == 0)      v = Whrz[(size_t)k * 1024 + col];
        else if (g == 1) v = Whrz[(size_t)k * 1024 + 512 + col];
        else             v = Whn[(size_t)k * 512 + col];
        Wt[c * WSTR + k] = v;
    }

    const int tx = tid & 15;                  // local hidden col
    const int ty = tid >> 4;                  // 0..15
    const int j = hs * 16 + tx;               // global hidden col
    const float bn_bias = bhn[j];
    const int r0 = ty * 2, r1 = r0 + 1;
    const int b0g = mi * 32 + r0;
    const int b1g = b0g + 1;

    const float* wrp = Wt + (size_t)tx * WSTR;
    const float* wzp = Wt + (size_t)(16 + tx) * WSTR;
    const float* wnp = Wt + (size_t)(32 + tx) * WSTR;
    const float* hp0 = Hs + r0 * 512;
    const float* hp1 = Hs + r1 * 512;

    __syncthreads();

    for (int t = 0; t < T_STEPS; ++t) {
        // -- prefetch step operands (independent of barrier) --
        const float* xb0 = g_xproj + ((size_t)t * B_BATCH + b0g) * 1536 + j;
        const float* xb1 = g_xproj + ((size_t)t * B_BATCH + b1g) * 1536 + j;
        float xr0 = __ldcs(xb0), xz0 = __ldcs(xb0 + 512), xn0 = __ldcs(xb0 + 1024);
        float xr1 = __ldcs(xb1), xz1 = __ldcs(xb1 + 512), xn1 = __ldcs(xb1 + 1024);
        if (tid < 32) rst_s[tid] = resets[t * B_BATCH + mi * 32 + tid];

        const float* hsrc = (t == 0)
            ? (h0 + (size_t)(mi * 32) * H_DIM)
            : (ys + ((size_t)(t - 1) * B_BATCH + mi * 32) * H_DIM);

        unsigned long long ar0 = 0, br0 = 0, az0 = 0, bz0 = 0, an0 = 0, bn0 = 0;
        unsigned long long ar1 = 0, br1 = 0, az1 = 0, bz1 = 0, an1 = 0, bn1 = 0;

#pragma unroll
        for (int half = 0; half < 2; ++half) {
            // wait for the 16 producers of this K-half (group mi, step t-1)
            if (t > 0) {
                if (tid == 0) {
                    volatile unsigned* vb = &g_bar[t - 1][mi][half];
                    while (*vb < 16u) __nanosleep(32);
                }
            }
            __syncthreads();  // releases waiters; also publishes rst_s (half 0)

            // load masked h tile half: cols [half*256, half*256+256)
            const int co = half * 256;
            for (int v = tid; v < 32 * 64; v += 256) {
                int row = v >> 6;
                int c4 = v & 63;
                float4 x = __ldcg((const float4*)(hsrc + (size_t)row * H_DIM + co) + c4);
                if (rst_s[row]) { x.x = 0.f; x.y = 0.f; x.z = 0.f; x.w = 0.f; }
                *((float4*)(Hs + row * 512 + co) + c4) = x;
            }
            __syncthreads();

            // GEMM over this K-half: 2 rows x 3 gates, 12 independent accs
#pragma unroll 4
            for (int k = co; k < co + 256; k += 4) {
                ulonglong2 a0 = *(const ulonglong2*)(hp0 + k);
                ulonglong2 a1 = *(const ulonglong2*)(hp1 + k);
                ulonglong2 wrv = *(const ulonglong2*)(wrp + k);
                ulonglong2 wzv = *(const ulonglong2*)(wzp + k);
                ulonglong2 wnv = *(const ulonglong2*)(wnp + k);
                fma2(ar0, a0.x, wrv.x); fma2(br0, a0.y, wrv.y);
                fma2(az0, a0.x, wzv.x); fma2(bz0, a0.y, wzv.y);
                fma2(an0, a0.x, wnv.x); fma2(bn0, a0.y, wnv.y);
                fma2(ar1, a1.x, wrv.x); fma2(br1, a1.y, wrv.y);
                fma2(az1, a1.x, wzv.x); fma2(bz1, a1.y, wzv.y);
                fma2(an1, a1.x, wnv.x); fma2(bn1, a1.y, wnv.y);
            }
        }

        float2 p, q;
        p = unpack2(ar0); q = unpack2(br0); float hr0 = (p.x + p.y) + (q.x + q.y);
        p = unpack2(az0); q = unpack2(bz0); float hz0 = (p.x + p.y) + (q.x + q.y);
        p = unpack2(an0); q = unpack2(bn0); float hn0 = (p.x + p.y) + (q.x + q.y);
        p = unpack2(ar1); q = unpack2(br1); float hr1 = (p.x + p.y) + (q.x + q.y);
        p = unpack2(az1); q = unpack2(bz1); float hz1 = (p.x + p.y) + (q.x + q.y);
        p = unpack2(an1); q = unpack2(bn1); float hn1 = (p.x + p.y) + (q.x + q.y);

        // gates + update (thread owns (b0g,j) and (b1g,j))
        {
            float hprev = hp0[j];
            float rg = 1.f / (1.f + __expf(-(xr0 + hr0)));
            float zg = 1.f / (1.f + __expf(-(xz0 + hz0)));
            float ng = tanhf(xn0 + rg * (hn0 + bn_bias));
            float hnew = (1.f - zg) * ng + zg * hprev;
            __stcg(&ys[((size_t)t * B_BATCH + b0g) * H_DIM + j], hnew);
            if (t == T_STEPS - 1) hT[(size_t)b0g * H_DIM + j] = hnew;
        }
        {
            float hprev = hp1[j];
            float rg = 1.f / (1.f + __expf(-(xr1 + hr1)));
            float zg = 1.f / (1.f + __expf(-(xz1 + hz1)));
            float ng = tanhf(xn1 + rg * (hn1 + bn_bias));
            float hnew = (1.f - zg) * ng + zg * hprev;
            __stcg(&ys[((size_t)t * B_BATCH + b1g) * H_DIM + j], hnew);
            if (t == T_STEPS - 1) hT[(size_t)b1g * H_DIM + j] = hnew;
        }

        // signal: this CTA's cols (half_id) of step t are done
        __threadfence();
        __syncthreads();
        if (tid == 0) atomicAdd(&g_bar[t][mi][half_id], 1u);
    }
}

extern "C" void kernel_launch(void* const* d_in, const int* in_sizes, int n_in,
                              void* d_out, int out_size) {
    const float* ins    = (const float*)d_in[0];   // [T,B,D]
    const int*   resets = (const int*)  d_in[1];   // [T,B] (bool -> int32)
    const float* h0     = (const float*)d_in[2];   // [B,H]
    const float* Wi     = (const float*)d_in[3];   // [D,3H]
    const float* bi     = (const float*)d_in[4];   // [3H]
    const float* Whrz   = (const float*)d_in[5];   // [H,2H]
    const float* Whn    = (const float*)d_in[6];   // [H,H]
    const float* bhn    = (const float*)d_in[7];   // [H]
    float* out = (float*)d_out;                    // hT [B*H], then ys [T*B*H]

    (void)in_sizes; (void)n_in; (void)out_size;

    const int scan_smem = (48 * WSTR + 32 * 512) * (int)sizeof(float);
    cudaFuncSetAttribute(gru_kernel,
                         cudaFuncAttributeMaxDynamicSharedMemorySize, scan_smem);

    init_bar_kernel<<<8, 512>>>();
    {
        dim3 grid(1536 / 128, (T_STEPS * B_BATCH) / 128);
        xproj_kernel<<<grid, 256>>>(ins, Wi, bi);
    }
    gru_kernel<<<128, 256, scan_smem>>>(resets, h0, Whrz, Whn, bhn, out);
}

// round 4
// speedup vs baseline: 1.4947x; 1.2604x over previous
#include <cuda_runtime.h>
#include <cstdint>
#include <cstddef>

#define T_STEPS 512
#define B_BATCH 128
#define D_IN    512
#define H_DIM   512

// Scratch (allocation-free rule: __device__ globals)
__device__ float    g_xproj[(size_t)T_STEPS * B_BATCH * 3 * H_DIM]; // [T,B,3H]
__device__ float    g_hT[2][(size_t)H_DIM * B_BATCH];               // [buf][k][row]
__device__ unsigned g_bar[T_STEPS][4];                              // [t][mi], 32 producers

// ---------- packed f32x2 helpers (sm_103a) ----------
static __device__ __forceinline__ unsigned long long pack2(float lo, float hi) {
    unsigned long long r;
    asm("mov.b64 %0, {%1, %2};" : "=l"(r) : "f"(lo), "f"(hi));
    return r;
}
static __device__ __forceinline__ void fma2(unsigned long long& d,
                                            unsigned long long a,
                                            unsigned long long b) {
    asm("fma.rn.f32x2 %0, %1, %2, %0;" : "+l"(d) : "l"(a), "l"(b));
}
static __device__ __forceinline__ void add2(unsigned long long& d,
                                            unsigned long long a) {
    asm("add.rn.f32x2 %0, %0, %1;" : "+l"(d) : "l"(a));
}
static __device__ __forceinline__ float2 unpack2(unsigned long long v) {
    float2 f;
    asm("mov.b64 {%0, %1}, %2;" : "=f"(f.x), "=f"(f.y) : "l"(v));
    return f;
}

// ---------- helper: reset barriers + transpose h0 into g_hT[1] ----------
__global__ void scan_prep_kernel(const float* __restrict__ h0) {
    if (blockIdx.x == 0) {
        for (int i = threadIdx.x; i < T_STEPS * 4; i += 256)
            ((unsigned*)g_bar)[i] = 0u;
    } else {
        int idx = (blockIdx.x - 1) * 256 + threadIdx.x;   // 0..65535
        int j = idx >> 7;           // hidden index (k)
        int b = idx & 127;          // batch row
        g_hT[1][(size_t)j * B_BATCH + b] = h0[(size_t)b * H_DIM + j];
    }
}

// ---------- x_proj GEMM: C[65536,1536] = A[65536,512] @ Wi[512,1536] + bi ----------
__global__ __launch_bounds__(256) void xproj_kernel(const float* __restrict__ A,
                                                    const float* __restrict__ W,
                                                    const float* __restrict__ bi) {
    __shared__ __align__(16) float As[2][16][132];
    __shared__ __align__(16) float Bs[2][16][128];

    const int tid = threadIdx.x;
    const int m0 = blockIdx.y * 128;
    const int n0 = blockIdx.x * 128;
    const int tx = tid & 15;
    const int ty = tid >> 4;

    const int arow = tid >> 1;
    const int acol = (tid & 1) << 3;
    const int brow = tid >> 5;
    const int bcol = (tid & 31) << 2;

    const float* Ag = A + (size_t)(m0 + arow) * D_IN + acol;
    const float* Bg = W + (size_t)brow * 1536 + n0 + bcol;

    unsigned long long acc[8][4];
#pragma unroll
    for (int i = 0; i < 8; ++i)
#pragma unroll
        for (int jj = 0; jj < 4; ++jj) acc[i][jj] = 0ull;

    float4 ra0 = *(const float4*)(Ag);
    float4 ra1 = *(const float4*)(Ag + 4);
    float4 rb0 = *(const float4*)(Bg);
    float4 rb1 = *(const float4*)(Bg + 8 * 1536);
    As[0][acol + 0][arow] = ra0.x; As[0][acol + 1][arow] = ra0.y;
    As[0][acol + 2][arow] = ra0.z; As[0][acol + 3][arow] = ra0.w;
    As[0][acol + 4][arow] = ra1.x; As[0][acol + 5][arow] = ra1.y;
    As[0][acol + 6][arow] = ra1.z; As[0][acol + 7][arow] = ra1.w;
    *(float4*)&Bs[0][brow][bcol] = rb0;
    *(float4*)&Bs[0][brow + 8][bcol] = rb1;
    __syncthreads();

    int buf = 0;
    for (int kt = 0; kt < 32; ++kt) {
        if (kt < 31) {
            const float* Ag2 = Ag + (kt + 1) * 16;
            const float* Bg2 = Bg + (size_t)(kt + 1) * 16 * 1536;
            ra0 = *(const float4*)(Ag2);
            ra1 = *(const float4*)(Ag2 + 4);
            rb0 = *(const float4*)(Bg2);
            rb1 = *(const float4*)(Bg2 + 8 * 1536);
        }
#pragma unroll
        for (int k = 0; k < 16; ++k) {
            ulonglong2 bA = *(const ulonglong2*)&Bs[buf][k][tx * 8];
            ulonglong2 bB = *(const ulonglong2*)&Bs[buf][k][tx * 8 + 4];
            float4 a03 = *(const float4*)&As[buf][k][ty * 8];
            float4 a47 = *(const float4*)&As[buf][k][ty * 8 + 4];
            float av[8] = {a03.x, a03.y, a03.z, a03.w, a47.x, a47.y, a47.z, a47.w};
#pragma unroll
            for (int i = 0; i < 8; ++i) {
                unsigned long long a2 = pack2(av[i], av[i]);
                fma2(acc[i][0], a2, bA.x);
                fma2(acc[i][1], a2, bA.y);
                fma2(acc[i][2], a2, bB.x);
                fma2(acc[i][3], a2, bB.y);
            }
        }
        if (kt < 31) {
            int nb = buf ^ 1;
            As[nb][acol + 0][arow] = ra0.x; As[nb][acol + 1][arow] = ra0.y;
            As[nb][acol + 2][arow] = ra0.z; As[nb][acol + 3][arow] = ra0.w;
            As[nb][acol + 4][arow] = ra1.x; As[nb][acol + 5][arow] = ra1.y;
            As[nb][acol + 6][arow] = ra1.z; As[nb][acol + 7][arow] = ra1.w;
            *(float4*)&Bs[nb][brow][bcol] = rb0;
            *(float4*)&Bs[nb][brow + 8][bcol] = rb1;
            __syncthreads();
            buf = nb;
        }
    }

    float4 bv0 = *(const float4*)&bi[n0 + tx * 8];
    float4 bv1 = *(const float4*)&bi[n0 + tx * 8 + 4];
#pragma unroll
    for (int i = 0; i < 8; ++i) {
        float2 p0 = unpack2(acc[i][0]);
        float2 p1 = unpack2(acc[i][1]);
        float2 p2 = unpack2(acc[i][2]);
        float2 p3 = unpack2(acc[i][3]);
        float4 o0, o1;
        o0.x = p0.x + bv0.x; o0.y = p0.y + bv0.y;
        o0.z = p1.x + bv0.z; o0.w = p1.y + bv0.w;
        o1.x = p2.x + bv1.x; o1.y = p2.y + bv1.y;
        o1.z = p3.x + bv1.z; o1.w = p3.y + bv1.w;
        float* dst = g_xproj + (size_t)(m0 + ty * 8 + i) * 1536 + n0 + tx * 8;
        *(float4*)dst = o0;
        *(float4*)(dst + 4) = o1;
    }
}

// ---------- persistent GRU scan ----------
// 128 CTAs: mi = bid>>5 (32 batch rows), hs = bid&31 (16 hidden cols = 48 out cols).
// SMEM: Wt[512][48] (c = hcol*3+gate), Hs[512][32] (k-major masked h tile).
// GEMM: warp = K-chunk of 64, thread tile 8 rows x 6 cols (col-pair FFMA2),
// partials reduced across 8 chunks via smem overlay on Hs.
__global__ __launch_bounds__(256) void gru_kernel(const int* __restrict__ resets,
                                                  const float* __restrict__ Whrz,
                                                  const float* __restrict__ Whn,
                                                  const float* __restrict__ bhn,
                                                  float* out) {
    extern __shared__ float smem[];
    float* Wt = smem;                        // [512][48]
    float* Hs = smem + 512 * 48;             // [512][32]
    __shared__ float mask_s[32];

    const int tid = threadIdx.x;
    const int lane = tid & 31;
    const int wid = tid >> 5;                // == K-chunk id (0..7)
    const int mi = blockIdx.x >> 5;
    const int hs = blockIdx.x & 31;

    float* hT = out;                             // [B,H]
    float* ys = out + (size_t)B_BATCH * H_DIM;   // [T,B,H]

    // one-time: weight slice into smem, layout Wt[k][hcol*3 + gate]
    for (int idx = tid; idx < 512 * 48; idx += 256) {
        int k = idx / 48;
        int c = idx - k * 48;
        int hcol = c / 3;
        int g = c - hcol * 3;
        int col = hs * 16 + hcol;
        float v;
        if (g == 0)      v = Whrz[(size_t)k * 1024 + col];
        else if (g == 1) v = Whrz[(size_t)k * 1024 + 512 + col];
        else             v = Whn[(size_t)k * 512 + col];
        Wt[idx] = v;
    }

    // GEMM-role indices
    const int rowg = lane >> 3;              // 0..3 (8 rows each)
    const int mg = lane & 7;                 // hpair 0..7
    // gate-role indices
    const int gr = tid >> 3;                 // 0..31 (batch row within tile)
    const int gm = tid & 7;                  // hpair
    const int j0 = hs * 16 + 2 * gm;
    const int j1 = j0 + 1;
    const int growg = mi * 32 + gr;          // global batch row
    const float bn0 = bhn[j0];
    const float bn1 = bhn[j1];

    unsigned long long* P = (unsigned long long*)Hs;  // partials overlay [8][32][25]

    __syncthreads();

    for (int t = 0; t < T_STEPS; ++t) {
        // prefetch x-projection operands (always ready; hides DRAM/L2 latency)
        const float* xb = g_xproj + ((size_t)t * B_BATCH + growg) * 1536 + j0;
        float2 xr2 = __ldcs((const float2*)(xb));
        float2 xz2 = __ldcs((const float2*)(xb + 512));
        float2 xn2 = __ldcs((const float2*)(xb + 1024));

        if (tid < 32)
            mask_s[tid] = resets[t * B_BATCH + mi * 32 + tid] ? 0.f : 1.f;

        // wait for the 32 producers of group mi at step t-1
        if (t > 0 && tid == 0) {
            volatile unsigned* vb = &g_bar[t - 1][mi];
            while (*vb < 32u) __nanosleep(32);
        }
        __syncthreads();

        // stage masked h tile, k-major: Hs[k][row]. lane == row.
        {
            const float* src = g_hT[(t + 1) & 1] + mi * 32 + lane;
            const float mk = mask_s[lane];
            const int kb = wid * 64;
#pragma unroll 8
            for (int kk = 0; kk < 64; ++kk) {
                float v = __ldcg(&src[(size_t)(kb + kk) * B_BATCH]);
                Hs[(kb + kk) * 32 + lane] = v * mk;
            }
        }
        __syncthreads();

        // hprev (masked) for the gate blend — read before partials overlay
        float hprev0 = Hs[j0 * 32 + gr];
        float hprev1 = Hs[j1 * 32 + gr];

        // GEMM over this warp's K-chunk: 8 rows x 3 col-pair accumulators
        unsigned long long acc[8][3];
#pragma unroll
        for (int i = 0; i < 8; ++i) { acc[i][0] = 0; acc[i][1] = 0; acc[i][2] = 0; }
        {
            const int kb = wid * 64;
            const float* wb = Wt + mg * 6;
#pragma unroll 4
            for (int kk = 0; kk < 64; ++kk) {
                const int k = kb + kk;
                float4 h03 = *(const float4*)&Hs[k * 32 + rowg * 8];
                float4 h47 = *(const float4*)&Hs[k * 32 + rowg * 8 + 4];
                unsigned long long w0 = *(const unsigned long long*)&wb[k * 48];
                unsigned long long w1 = *(const unsigned long long*)&wb[k * 48 + 2];
                unsigned long long w2 = *(const unsigned long long*)&wb[k * 48 + 4];
                float hv[8] = {h03.x, h03.y, h03.z, h03.w, h47.x, h47.y, h47.z, h47.w};
#pragma unroll
                for (int i = 0; i < 8; ++i) {
                    unsigned long long a2 = pack2(hv[i], hv[i]);
                    fma2(acc[i][0], a2, w0);
                    fma2(acc[i][1], a2, w1);
                    fma2(acc[i][2], a2, w2);
                }
            }
        }
        __syncthreads();   // Hs fully consumed -> safe to overlay partials

        // write partials: P[(kc*32 + row)*25 + m*3 + cp]
#pragma unroll
        for (int i = 0; i < 8; ++i) {
            int base = (wid * 32 + rowg * 8 + i) * 25 + mg * 3;
            P[base + 0] = acc[i][0];
            P[base + 1] = acc[i][1];
            P[base + 2] = acc[i][2];
        }
        __syncthreads();

        // reduce across 8 K-chunks (gate thread: row gr, hpair gm)
        unsigned long long s0 = 0, s1 = 0, s2 = 0;
#pragma unroll
        for (int kc = 0; kc < 8; ++kc) {
            int base = (kc * 32 + gr) * 25 + gm * 3;
            add2(s0, P[base + 0]);
            add2(s1, P[base + 1]);
            add2(s2, P[base + 2]);
        }
        float2 u0 = unpack2(s0);   // (hr[j0], hz[j0])
        float2 u1 = unpack2(s1);   // (hn[j0], hr[j1])
        float2 u2 = unpack2(s2);   // (hz[j1], hn[j1])

        // gates + state update for (growg, j0) and (growg, j1)
        float rg0 = 1.f / (1.f + __expf(-(xr2.x + u0.x)));
        float zg0 = 1.f / (1.f + __expf(-(xz2.x + u0.y)));
        float ng0 = tanhf(xn2.x + rg0 * (u1.x + bn0));
        float h0n = (1.f - zg0) * ng0 + zg0 * hprev0;

        float rg1 = 1.f / (1.f + __expf(-(xr2.y + u1.y)));
        float zg1 = 1.f / (1.f + __expf(-(xz2.y + u2.x)));
        float ng1 = tanhf(xn2.y + rg1 * (u2.y + bn1));
        float h1n = (1.f - zg1) * ng1 + zg1 * hprev1;

        float2 o; o.x = h0n; o.y = h1n;
        *(float2*)&ys[((size_t)t * B_BATCH + growg) * H_DIM + j0] = o;
        float* ht = g_hT[t & 1];
        ht[(size_t)j0 * B_BATCH + growg] = h0n;
        ht[(size_t)j1 * B_BATCH + growg] = h1n;
        if (t == T_STEPS - 1)
            *(float2*)&hT[(size_t)growg * H_DIM + j0] = o;

        __threadfence();
        __syncthreads();
        if (tid == 0) atomicAdd(&g_bar[t][mi], 1u);
    }
}

extern "C" void kernel_launch(void* const* d_in, const int* in_sizes, int n_in,
                              void* d_out, int out_size) {
    const float* ins    = (const float*)d_in[0];   // [T,B,D]
    const int*   resets = (const int*)  d_in[1];   // [T,B]
    const float* h0     = (const float*)d_in[2];   // [B,H]
    const float* Wi     = (const float*)d_in[3];   // [D,3H]
    const float* bi     = (const float*)d_in[4];   // [3H]
    const float* Whrz   = (const float*)d_in[5];   // [H,2H]
    const float* Whn    = (const float*)d_in[6];   // [H,H]
    const float* bhn    = (const float*)d_in[7];   // [H]
    float* out = (float*)d_out;                    // hT [B*H], then ys [T*B*H]

    (void)in_sizes; (void)n_in; (void)out_size;

    const int scan_smem = (512 * 48 + 512 * 32) * (int)sizeof(float);  // 160 KB
    cudaFuncSetAttribute(gru_kernel,
                         cudaFuncAttributeMaxDynamicSharedMemorySize, scan_smem);

    scan_prep_kernel<<<257, 256>>>(h0);
    {
        dim3 grid(1536 / 128, (T_STEPS * B_BATCH) / 128);
        xproj_kernel<<<grid, 256>>>(ins, Wi, bi);
    }
    gru_kernel<<<128, 256, scan_smem>>>(resets, Whrz, Whn, bhn, out);
}

// round 6
// speedup vs baseline: 1.7108x; 1.1446x over previous
#include <cuda_runtime.h>
#include <cuda_bf16.h>
#include <cstdint>
#include <cstddef>

#define T_STEPS 512
#define B_BATCH 128
#define D_IN    512
#define H_DIM   512

// Scratch (allocation-free rule: __device__ globals)
__device__ float    g_xproj[(size_t)T_STEPS * B_BATCH * 3 * H_DIM]; // [T,B,3H]
__device__ float    g_hT[2][(size_t)H_DIM * B_BATCH];               // [buf][k][row]
__device__ unsigned g_bar[T_STEPS][4];                              // [t][mi], 32 producers

// ---------- packed f32x2 helpers (sm_103a baseline ISA) ----------
static __device__ __forceinline__ unsigned long long pack2(float lo, float hi) {
    unsigned long long r;
    asm("mov.b64 %0, {%1, %2};" : "=l"(r) : "f"(lo), "f"(hi));
    return r;
}
static __device__ __forceinline__ void fma2(unsigned long long& d,
                                            unsigned long long a,
                                            unsigned long long b) {
    asm("fma.rn.f32x2 %0, %1, %2, %0;" : "+l"(d) : "l"(a), "l"(b));
}
static __device__ __forceinline__ void add2(unsigned long long& d,
                                            unsigned long long a) {
    asm("add.rn.f32x2 %0, %0, %1;" : "+l"(d) : "l"(a));
}
static __device__ __forceinline__ float2 unpack2(unsigned long long v) {
    float2 f;
    asm("mov.b64 {%0, %1}, %2;" : "=f"(f.x), "=f"(f.y) : "l"(v));
    return f;
}

// ---------- mma.sync helpers (base sm_80+ PTX, safe under compute_103) ----------
static __device__ __forceinline__ uint32_t smem_u32(const void* p) {
    uint32_t a;
    asm("{ .reg .u64 t; cvta.to.shared.u64 t, %1; cvt.u32.u64 %0, t; }"
        : "=r"(a) : "l"(p));
    return a;
}
static __device__ __forceinline__ void ldsm_x4(uint32_t& r0, uint32_t& r1,
                                               uint32_t& r2, uint32_t& r3,
                                               uint32_t addr) {
    asm volatile("ldmatrix.sync.aligned.m8n8.x4.shared.b16 {%0,%1,%2,%3}, [%4];"
                 : "=r"(r0), "=r"(r1), "=r"(r2), "=r"(r3) : "r"(addr));
}
static __device__ __forceinline__ void mma_bf16(float& c0, float& c1, float& c2, float& c3,
                                                uint32_t a0, uint32_t a1, uint32_t a2, uint32_t a3,
                                                uint32_t b0, uint32_t b1) {
    asm volatile("mma.sync.aligned.m16n8k16.row.col.f32.bf16.bf16.f32 "
                 "{%0,%1,%2,%3}, {%4,%5,%6,%7}, {%8,%9}, {%0,%1,%2,%3};"
                 : "+f"(c0), "+f"(c1), "+f"(c2), "+f"(c3)
                 : "r"(a0), "r"(a1), "r"(a2), "r"(a3), "r"(b0), "r"(b1));
}
static __device__ __forceinline__ uint32_t bf16x2_of(float lo, float hi) {
    __nv_bfloat16 a = __float2bfloat16_rn(lo);
    __nv_bfloat16 b = __float2bfloat16_rn(hi);
    return (uint32_t)__bfloat16_as_ushort(a) | ((uint32_t)__bfloat16_as_ushort(b) << 16);
}

// ---------- helper: reset barriers + transpose h0 into g_hT[1] ----------
__global__ void scan_prep_kernel(const float* __restrict__ h0) {
    if (blockIdx.x == 0) {
        for (int i = threadIdx.x; i < T_STEPS * 4; i += 256)
            ((unsigned*)g_bar)[i] = 0u;
    } else {
        int idx = (blockIdx.x - 1) * 256 + threadIdx.x;   // 0..65535
        int j = idx >> 7;           // hidden index (k)
        int b = idx & 127;          // batch row
        g_hT[1][(size_t)j * B_BATCH + b] = h0[(size_t)b * H_DIM + j];
    }
}

// ---------------- x_proj GEMM via mma.sync split-bf16 ----------------
// C[65536,1536] = A[65536,512] @ W[512,1536] + bi
// D = Ah@Wh + Al@Wh + Ah@Wl   (term Al@Wl ~2^-16, dropped)
// CTA tile 128x128, k-chunk 32, double-buffered. Warp tile 64x32 (2x4 warps).
// SMEM rows padded to 40 bf16 (80B) -> ldmatrix conflict-free.
#define XP_ROWSTR 40                      // bf16 per smem row
#define XP_PLANE  (128 * XP_ROWSTR)      // 5120 bf16
#define XP_BUF    (4 * XP_PLANE)         // AH, AL, WH, WL
#define XP_SMEM_BYTES (2 * XP_BUF * 2)   // 81920

__global__ __launch_bounds__(256, 1) void xproj_kernel(const float* __restrict__ A,
                                                       const float* __restrict__ W,
                                                       const float* __restrict__ bi) {
    extern __shared__ __align__(16) __nv_bfloat16 sm[];
    const int tid = threadIdx.x;
    const int lane = tid & 31;
    const int wid = tid >> 5;
    const int warp_m = wid & 1;          // 2 m-groups of 64 rows
    const int warp_n = wid >> 1;         // 4 n-groups of 32 cols
    const int m0 = blockIdx.y * 128;
    const int n0 = blockIdx.x * 128;

    float acc[4][4][4];
#pragma unroll
    for (int i = 0; i < 4; ++i)
#pragma unroll
        for (int jn = 0; jn < 4; ++jn)
#pragma unroll
            for (int q = 0; q < 4; ++q) acc[i][jn][q] = 0.f;

    // staging register arrays
    float2 ra[8];       // A pairs
    float  rw0[8], rw1[8];  // W pairs (k, k+1)

    // ldmatrix per-lane byte offsets
    const uint32_t a_lane_off = (uint32_t)((lane & 15) * (XP_ROWSTR * 2) + (lane >> 4) * 16);
    const uint32_t b_lane_off = (uint32_t)(((lane & 7) + ((lane >> 4) << 3)) * (XP_ROWSTR * 2)
                                           + ((lane >> 3) & 1) * 16);

    const uint32_t sm_base = smem_u32(sm);

    // ---- stage chunk 0 into buffer 0 ----
    {
        const int k0 = 0;
#pragma unroll
        for (int i = 0; i < 8; ++i) {
            int p = i * 256 + tid;
            int r = p >> 4, cp = p & 15;
            ra[i] = *(const float2*)&A[(size_t)(m0 + r) * D_IN + k0 + cp * 2];
            int n = p & 127, kp = p >> 7;
            rw0[i] = W[(size_t)(k0 + 2 * kp) * 1536 + n0 + n];
            rw1[i] = W[(size_t)(k0 + 2 * kp + 1) * 1536 + n0 + n];
        }
        uint32_t* AH = (uint32_t*)(sm);
        uint32_t* AL = (uint32_t*)(sm + XP_PLANE);
        uint32_t* WH = (uint32_t*)(sm + 2 * XP_PLANE);
        uint32_t* WL = (uint32_t*)(sm + 3 * XP_PLANE);
#pragma unroll
        for (int i = 0; i < 8; ++i) {
            int p = i * 256 + tid;
            int r = p >> 4, cp = p & 15;
            float h0v = __bfloat162float(__float2bfloat16_rn(ra[i].x));
            float h1v = __bfloat162float(__float2bfloat16_rn(ra[i].y));
            AH[r * (XP_ROWSTR / 2) + cp] = bf16x2_of(ra[i].x, ra[i].y);
            AL[r * (XP_ROWSTR / 2) + cp] = bf16x2_of(ra[i].x - h0v, ra[i].y - h1v);
            int n = p & 127, kp = p >> 7;
            float w0h = __bfloat162float(__float2bfloat16_rn(rw0[i]));
            float w1h = __bfloat162float(__float2bfloat16_rn(rw1[i]));
            WH[n * (XP_ROWSTR / 2) + kp] = bf16x2_of(rw0[i], rw1[i]);
            WL[n * (XP_ROWSTR / 2) + kp] = bf16x2_of(rw0[i] - w0h, rw1[i] - w1h);
        }
    }
    __syncthreads();

    int buf = 0;
    for (int kt = 0; kt < 16; ++kt) {
        // prefetch next chunk into registers
        if (kt < 15) {
            const int k0 = (kt + 1) * 32;
#pragma unroll
            for (int i = 0; i < 8; ++i) {
                int p = i * 256 + tid;
                int r = p >> 4, cp = p & 15;
                ra[i] = *(const float2*)&A[(size_t)(m0 + r) * D_IN + k0 + cp * 2];
                int n = p & 127, kp = p >> 7;
                rw0[i] = W[(size_t)(k0 + 2 * kp) * 1536 + n0 + n];
                rw1[i] = W[(size_t)(k0 + 2 * kp + 1) * 1536 + n0 + n];
            }
        }

        // MMAs on current buffer
        const uint32_t bb = sm_base + (uint32_t)(buf * XP_BUF * 2);
        const uint32_t baseAH = bb;
        const uint32_t baseAL = bb + XP_PLANE * 2;
        const uint32_t baseWH = bb + 2 * XP_PLANE * 2;
        const uint32_t baseWL = bb + 3 * XP_PLANE * 2;
#pragma unroll
        for (int k16 = 0; k16 < 2; ++k16) {
            const uint32_t kadd = (uint32_t)(k16 * 32);
            uint32_t ah[4][4], al[4][4], bh[4][2], bl[4][2];
#pragma unroll
            for (int mt = 0; mt < 4; ++mt) {
                uint32_t ro = (uint32_t)((warp_m * 64 + mt * 16) * (XP_ROWSTR * 2));
                ldsm_x4(ah[mt][0], ah[mt][1], ah[mt][2], ah[mt][3],
                        baseAH + ro + a_lane_off + kadd);
                ldsm_x4(al[mt][0], al[mt][1], al[mt][2], al[mt][3],
                        baseAL + ro + a_lane_off + kadd);
            }
#pragma unroll
            for (int nt2 = 0; nt2 < 2; ++nt2) {
                uint32_t no = (uint32_t)((warp_n * 32 + nt2 * 16) * (XP_ROWSTR * 2));
                ldsm_x4(bh[nt2 * 2][0], bh[nt2 * 2][1], bh[nt2 * 2 + 1][0], bh[nt2 * 2 + 1][1],
                        baseWH + no + b_lane_off + kadd);
                ldsm_x4(bl[nt2 * 2][0], bl[nt2 * 2][1], bl[nt2 * 2 + 1][0], bl[nt2 * 2 + 1][1],
                        baseWL + no + b_lane_off + kadd);
            }
#pragma unroll
            for (int mt = 0; mt < 4; ++mt)
#pragma unroll
                for (int nt = 0; nt < 4; ++nt) {
                    float* c = acc[mt][nt];
                    mma_bf16(c[0], c[1], c[2], c[3],
                             ah[mt][0], ah[mt][1], ah[mt][2], ah[mt][3],
                             bh[nt][0], bh[nt][1]);
                    mma_bf16(c[0], c[1], c[2], c[3],
                             al[mt][0], al[mt][1], al[mt][2], al[mt][3],
                             bh[nt][0], bh[nt][1]);
                    mma_bf16(c[0], c[1], c[2], c[3],
                             ah[mt][0], ah[mt][1], ah[mt][2], ah[mt][3],
                             bl[nt][0], bl[nt][1]);
                }
        }

        // store prefetched chunk into other buffer
        if (kt < 15) {
            __syncthreads();   // everyone done reading next buffer from 2 chunks ago
            int nb = buf ^ 1;
            __nv_bfloat16* sb = sm + nb * XP_BUF;
            uint32_t* AH = (uint32_t*)(sb);
            uint32_t* AL = (uint32_t*)(sb + XP_PLANE);
            uint32_t* WH = (uint32_t*)(sb + 2 * XP_PLANE);
            uint32_t* WL = (uint32_t*)(sb + 3 * XP_PLANE);
#pragma unroll
            for (int i = 0; i < 8; ++i) {
                int p = i * 256 + tid;
                int r = p >> 4, cp = p & 15;
                float h0v = __bfloat162float(__float2bfloat16_rn(ra[i].x));
                float h1v = __bfloat162float(__float2bfloat16_rn(ra[i].y));
                AH[r * (XP_ROWSTR / 2) + cp] = bf16x2_of(ra[i].x, ra[i].y);
                AL[r * (XP_ROWSTR / 2) + cp] = bf16x2_of(ra[i].x - h0v, ra[i].y - h1v);
                int n = p & 127, kp = p >> 7;
                float w0h = __bfloat162float(__float2bfloat16_rn(rw0[i]));
                float w1h = __bfloat162float(__float2bfloat16_rn(rw1[i]));
                WH[n * (XP_ROWSTR / 2) + kp] = bf16x2_of(rw0[i], rw1[i]);
                WL[n * (XP_ROWSTR / 2) + kp] = bf16x2_of(rw0[i] - w0h, rw1[i] - w1h);
            }
            __syncthreads();
            buf = nb;
        }
    }

    // epilogue: add bias, store fp32
#pragma unroll
    for (int nt = 0; nt < 4; ++nt) {
        int ncol = warp_n * 32 + nt * 8 + (lane & 3) * 2;
        float2 bv = *(const float2*)&bi[n0 + ncol];
#pragma unroll
        for (int mt = 0; mt < 4; ++mt) {
            int r = m0 + warp_m * 64 + mt * 16 + (lane >> 2);
            float* c = acc[mt][nt];
            float2 o0; o0.x = c[0] + bv.x; o0.y = c[1] + bv.y;
            float2 o1; o1.x = c[2] + bv.x; o1.y = c[3] + bv.y;
            *(float2*)&g_xproj[(size_t)r * 1536 + n0 + ncol] = o0;
            *(float2*)&g_xproj[(size_t)(r + 8) * 1536 + n0 + ncol] = o1;
        }
    }
}

// ---------------- persistent GRU scan (round-4 passing version, fp32) ----------------
__global__ __launch_bounds__(256) void gru_kernel(const int* __restrict__ resets,
                                                  const float* __restrict__ Whrz,
                                                  const float* __restrict__ Whn,
                                                  const float* __restrict__ bhn,
                                                  float* out) {
    extern __shared__ float smem[];
    float* Wt = smem;                        // [512][48]
    float* Hs = smem + 512 * 48;             // [512][32]
    __shared__ float mask_s[32];

    const int tid = threadIdx.x;
    const int lane = tid & 31;
    const int wid = tid >> 5;                // K-chunk id (0..7)
    const int mi = blockIdx.x >> 5;
    const int hs = blockIdx.x & 31;

    float* hT = out;                             // [B,H]
    float* ys = out + (size_t)B_BATCH * H_DIM;   // [T,B,H]

    for (int idx = tid; idx < 512 * 48; idx += 256) {
        int k = idx / 48;
        int c = idx - k * 48;
        int hcol = c / 3;
        int g = c - hcol * 3;
        int col = hs * 16 + hcol;
        float v;
        if (g == 0)      v = Whrz[(size_t)k * 1024 + col];
        else if (g == 1) v = Whrz[(size_t)k * 1024 + 512 + col];
        else             v = Whn[(size_t)k * 512 + col];
        Wt[idx] = v;
    }

    const int rowg = lane >> 3;
    const int mg = lane & 7;
    const int gr = tid >> 3;
    const int gm = tid & 7;
    const int j0 = hs * 16 + 2 * gm;
    const int j1 = j0 + 1;
    const int growg = mi * 32 + gr;
    const float bn0 = bhn[j0];
    const float bn1 = bhn[j1];

    unsigned long long* P = (unsigned long long*)Hs;  // partials overlay [8][32][25]

    __syncthreads();

    for (int t = 0; t < T_STEPS; ++t) {
        const float* xb = g_xproj + ((size_t)t * B_BATCH + growg) * 1536 + j0;
        float2 xr2 = __ldcs((const float2*)(xb));
        float2 xz2 = __ldcs((const float2*)(xb + 512));
        float2 xn2 = __ldcs((const float2*)(xb + 1024));

        if (tid < 32)
            mask_s[tid] = resets[t * B_BATCH + mi * 32 + tid] ? 0.f : 1.f;

        if (t > 0 && tid == 0) {
            volatile unsigned* vb = &g_bar[t - 1][mi];
            while (*vb < 32u) __nanosleep(32);
        }
        __syncthreads();

        {
            const float* src = g_hT[(t + 1) & 1] + mi * 32 + lane;
            const float mk = mask_s[lane];
            const int kb = wid * 64;
#pragma unroll 8
            for (int kk = 0; kk < 64; ++kk) {
                float v = __ldcg(&src[(size_t)(kb + kk) * B_BATCH]);
                Hs[(kb + kk) * 32 + lane] = v * mk;
            }
        }
        __syncthreads();

        float hprev0 = Hs[j0 * 32 + gr];
        float hprev1 = Hs[j1 * 32 + gr];

        unsigned long long acc[8][3];
#pragma unroll
        for (int i = 0; i < 8; ++i) { acc[i][0] = 0; acc[i][1] = 0; acc[i][2] = 0; }
        {
            const int kb = wid * 64;
            const float* wb = Wt + mg * 6;
#pragma unroll 4
            for (int kk = 0; kk < 64; ++kk) {
                const int k = kb + kk;
                float4 h03 = *(const float4*)&Hs[k * 32 + rowg * 8];
                float4 h47 = *(const float4*)&Hs[k * 32 + rowg * 8 + 4];
                unsigned long long w0 = *(const unsigned long long*)&wb[k * 48];
                unsigned long long w1 = *(const unsigned long long*)&wb[k * 48 + 2];
                unsigned long long w2 = *(const unsigned long long*)&wb[k * 48 + 4];
                float hv[8] = {h03.x, h03.y, h03.z, h03.w, h47.x, h47.y, h47.z, h47.w};
#pragma unroll
                for (int i = 0; i < 8; ++i) {
                    unsigned long long a2 = pack2(hv[i], hv[i]);
                    fma2(acc[i][0], a2, w0);
                    fma2(acc[i][1], a2, w1);
                    fma2(acc[i][2], a2, w2);
                }
            }
        }
        __syncthreads();

#pragma unroll
        for (int i = 0; i < 8; ++i) {
            int base = (wid * 32 + rowg * 8 + i) * 25 + mg * 3;
            P[base + 0] = acc[i][0];
            P[base + 1] = acc[i][1];
            P[base + 2] = acc[i][2];
        }
        __syncthreads();

        unsigned long long s0 = 0, s1 = 0, s2 = 0;
#pragma unroll
        for (int kc = 0; kc < 8; ++kc) {
            int base = (kc * 32 + gr) * 25 + gm * 3;
            add2(s0, P[base + 0]);
            add2(s1, P[base + 1]);
            add2(s2, P[base + 2]);
        }
        float2 u0 = unpack2(s0);
        float2 u1 = unpack2(s1);
        float2 u2 = unpack2(s2);

        float rg0 = 1.f / (1.f + __expf(-(xr2.x + u0.x)));
        float zg0 = 1.f / (1.f + __expf(-(xz2.x + u0.y)));
        float ng0 = tanhf(xn2.x + rg0 * (u1.x + bn0));
        float h0n = (1.f - zg0) * ng0 + zg0 * hprev0;

        float rg1 = 1.f / (1.f + __expf(-(xr2.y + u1.y)));
        float zg1 = 1.f / (1.f + __expf(-(xz2.y + u2.x)));
        float ng1 = tanhf(xn2.y + rg1 * (u2.y + bn1));
        float h1n = (1.f - zg1) * ng1 + zg1 * hprev1;

        float2 o; o.x = h0n; o.y = h1n;
        *(float2*)&ys[((size_t)t * B_BATCH + growg) * H_DIM + j0] = o;
        float* ht = g_hT[t & 1];
        ht[(size_t)j0 * B_BATCH + growg] = h0n;
        ht[(size_t)j1 * B_BATCH + growg] = h1n;
        if (t == T_STEPS - 1)
            *(float2*)&hT[(size_t)growg * H_DIM + j0] = o;

        __threadfence();
        __syncthreads();
        if (tid == 0) atomicAdd(&g_bar[t][mi], 1u);
    }
}

extern "C" void kernel_launch(void* const* d_in, const int* in_sizes, int n_in,
                              void* d_out, int out_size) {
    const float* ins    = (const float*)d_in[0];   // [T,B,D]
    const int*   resets = (const int*)  d_in[1];   // [T,B]
    const float* h0     = (const float*)d_in[2];   // [B,H]
    const float* Wi     = (const float*)d_in[3];   // [D,3H]
    const float* bi     = (const float*)d_in[4];   // [3H]
    const float* Whrz   = (const float*)d_in[5];   // [H,2H]
    const float* Whn    = (const float*)d_in[6];   // [H,H]
    const float* bhn    = (const float*)d_in[7];   // [H]
    float* out = (float*)d_out;                    // hT [B*H], then ys [T*B*H]

    (void)in_sizes; (void)n_in; (void)out_size;

    const int scan_smem = (512 * 48 + 512 * 32) * (int)sizeof(float);  // 160 KB
    cudaFuncSetAttribute(gru_kernel,
                         cudaFuncAttributeMaxDynamicSharedMemorySize, scan_smem);
    cudaFuncSetAttribute(xproj_kernel,
                         cudaFuncAttributeMaxDynamicSharedMemorySize, XP_SMEM_BYTES);

    scan_prep_kernel<<<257, 256>>>(h0);
    {
        dim3 grid(1536 / 128, (T_STEPS * B_BATCH) / 128);
        xproj_kernel<<<grid, 256, XP_SMEM_BYTES>>>(ins, Wi, bi);
    }
    gru_kernel<<<128, 256, scan_smem>>>(resets, Whrz, Whn, bhn, out);
}